// round 6
// baseline (speedup 1.0000x reference)
#include <cuda_runtime.h>
#include <math.h>
#include <stdint.h>

// ---------------- problem constants ----------------
#define BATCH   2
#define SEQLEN  2048
#define DMODEL  1024
#define ED      2048
#define NST     16
#define DTR     64
#define DCONV   4
#define ROWS    (BATCH*SEQLEN)      // 4096
#define DBCW    (DTR + 2*NST)       // 96
#define NCH     16
#define CH      (SEQLEN/NCH)        // 128

// ---------------- scratch ----------------
__device__ float g_xz   [(size_t)ROWS * 2 * ED];
__device__ float g_xc   [(size_t)ROWS * ED];
__device__ float g_dbc  [(size_t)ROWS * DBCW];
__device__ float g_delta[(size_t)ROWS * ED];
__device__ float g_yz   [(size_t)ROWS * ED];
__device__ float g_aprod[(size_t)BATCH * ED * NCH * NST];
__device__ float g_hend [(size_t)BATCH * ED * NCH * NST];
__device__ float g_h0   [(size_t)BATCH * ED * NCH * NST];

// ---------------- math helpers ----------------
__device__ __forceinline__ float ex2f(float x) {
    float y; asm("ex2.approx.f32 %0, %1;" : "=f"(y) : "f"(x)); return y;
}
__device__ __forceinline__ float siluf(float x) {
    return x / (1.f + ex2f(-1.4426950408889634f * x));
}
__device__ __forceinline__ float softplusf(float x) {
    return (x > 20.f) ? x : log1pf(__expf(x));
}

// ---------------- PTX helpers (plain sm_80+ features only) ----------------
__device__ __forceinline__ uint32_t smem_u32(const void* p) {
    uint32_t a;
    asm("{ .reg .u64 t; cvta.to.shared.u64 t, %1; cvt.u32.u64 %0, t; }" : "=r"(a) : "l"(p));
    return a;
}
__device__ __forceinline__ void cp16(uint32_t dst, const void* src) {
    asm volatile("cp.async.cg.shared.global [%0], [%1], 16;" :: "r"(dst), "l"(src));
}
__device__ __forceinline__ void cp16z(uint32_t dst, const void* src, uint32_t sz) {
    asm volatile("cp.async.cg.shared.global [%0], [%1], 16, %2;" :: "r"(dst), "l"(src), "r"(sz));
}
__device__ __forceinline__ void cp_commit() {
    asm volatile("cp.async.commit_group;" ::: "memory");
}
template<int N> __device__ __forceinline__ void cp_wait() {
    asm volatile("cp.async.wait_group %0;" :: "n"(N) : "memory");
}
__device__ __forceinline__ uint32_t f2tf(float x) {
    uint32_t u; asm("cvt.rna.tf32.f32 %0, %1;" : "=r"(u) : "f"(x)); return u;
}
__device__ __forceinline__ void mma8(float* c, const uint32_t* a, const uint32_t* b) {
    asm volatile(
        "mma.sync.aligned.m16n8k8.row.col.f32.tf32.tf32.f32 "
        "{%0,%1,%2,%3}, {%4,%5,%6,%7}, {%8,%9}, {%0,%1,%2,%3};"
        : "+f"(c[0]), "+f"(c[1]), "+f"(c[2]), "+f"(c[3])
        : "r"(a[0]), "r"(a[1]), "r"(a[2]), "r"(a[3]), "r"(b[0]), "r"(b[1]));
}

// ---------------- tf32 mma.sync GEMM: C[M,N] = A[M,K] @ B[N,K]^T ----------------
// 128x128 CTA tile, 4 warps (2m x 2n), 64x64 warp tile, BK=16, 4-stage cp.async.
// Smem stride 20 floats (conflict-free fragment fetch).
// EPI=1: softplus(acc + bias[n]).  ATOMIC=1: atomicAdd (split-K).  GUARDN=1: N<128 tile guard.
#define MM_STG_F   (128 * 20)              // floats per matrix per stage
#define MM_SMEM    (4 * 2 * MM_STG_F * 4)  // 81920 bytes

template<int EPI, int ATOMIC, int GUARDN>
__global__ void __launch_bounds__(128, 2)
gemm_mma(const float* __restrict__ A, const float* __restrict__ B,
         float* __restrict__ C, const float* __restrict__ bias,
         int M, int N, int K, int lda, int ldb, int ldc, int kSlice)
{
    extern __shared__ __align__(128) float sm[];
    const uint32_t sb = smem_u32(sm);
    const int tid  = threadIdx.x;
    const int lane = tid & 31;
    const int wid  = tid >> 5;           // 0..3
    const int wm   = wid >> 1;           // 0..1
    const int wn   = wid & 1;            // 0..1
    const int g    = lane >> 2;          // 0..7
    const int j    = lane & 3;           // 0..3
    const int mBlk = blockIdx.y * 128;
    const int nBlk = blockIdx.x * 128;
    const int kBeg = blockIdx.z * kSlice;
    const int T    = kSlice >> 4;

    float acc[4][8][4];
#pragma unroll
    for (int a = 0; a < 4; a++)
#pragma unroll
        for (int b = 0; b < 8; b++)
#pragma unroll
            for (int c = 0; c < 4; c++) acc[a][b][c] = 0.f;

    auto load_tile = [&](int kt, int s) {
        const int k0 = kBeg + kt * 16;
        const uint32_t aB = sb + (uint32_t)s * (2 * MM_STG_F * 4);
        const uint32_t bB = aB + MM_STG_F * 4;
#pragma unroll
        for (int i = 0; i < 4; i++) {
            int ch  = tid + i * 128;     // 0..511
            int row = ch >> 2;           // 0..127
            int c4  = ch & 3;            // 16B chunk
            cp16(aB + row * 80 + c4 * 16,
                 A + (size_t)(mBlk + row) * lda + k0 + c4 * 4);
            if (GUARDN) {
                int brow = nBlk + row;
                int bcl  = min(brow, N - 1);
                uint32_t sz = (brow < N) ? 16u : 0u;
                cp16z(bB + row * 80 + c4 * 16,
                      B + (size_t)bcl * ldb + k0 + c4 * 4, sz);
            } else {
                cp16(bB + row * 80 + c4 * 16,
                     B + (size_t)(nBlk + row) * ldb + k0 + c4 * 4);
            }
        }
        cp_commit();
    };

    load_tile(0, 0);
    load_tile(1, 1);
    load_tile(2, 2);

    for (int kt = 0; kt < T; kt++) {
        cp_wait<2>();
        __syncthreads();

        if (kt + 3 < T) load_tile(kt + 3, (kt + 3) & 3);
        cp_commit();     // always-commit -> loop-invariant wait count

        const int buf = kt & 3;
        const float* As = sm + (size_t)buf * (2 * MM_STG_F);
        const float* Bs = As + MM_STG_F;

#pragma unroll
        for (int ks = 0; ks < 2; ks++) {
            const int k0 = ks * 8;
            uint32_t af[4][4], bf[8][2];
#pragma unroll
            for (int mt = 0; mt < 4; mt++) {
                int r = wm * 64 + mt * 16 + g;
                af[mt][0] = f2tf(As[r * 20 + k0 + j]);
                af[mt][1] = f2tf(As[(r + 8) * 20 + k0 + j]);
                af[mt][2] = f2tf(As[r * 20 + k0 + j + 4]);
                af[mt][3] = f2tf(As[(r + 8) * 20 + k0 + j + 4]);
            }
#pragma unroll
            for (int nt = 0; nt < 8; nt++) {
                int r = wn * 64 + nt * 8 + g;
                bf[nt][0] = f2tf(Bs[r * 20 + k0 + j]);
                bf[nt][1] = f2tf(Bs[r * 20 + k0 + j + 4]);
            }
#pragma unroll
            for (int mt = 0; mt < 4; mt++)
#pragma unroll
                for (int nt = 0; nt < 8; nt++)
                    mma8(acc[mt][nt], af[mt], bf[nt]);
        }
    }

    // epilogue
#pragma unroll
    for (int mt = 0; mt < 4; mt++) {
#pragma unroll
        for (int nt = 0; nt < 8; nt++) {
            int m = mBlk + wm * 64 + mt * 16 + g;
            int n = nBlk + wn * 64 + nt * 8 + 2 * j;
            float* cv = acc[mt][nt];
            if (GUARDN && n >= N) continue;
            float v0 = cv[0], v1 = cv[1], v2 = cv[2], v3 = cv[3];
            if (EPI == 1) {
                float b0 = bias[n], b1 = bias[n + 1];
                v0 = softplusf(v0 + b0); v1 = softplusf(v1 + b1);
                v2 = softplusf(v2 + b0); v3 = softplusf(v3 + b1);
            }
            if (ATOMIC) {
                atomicAdd(&C[(size_t)m * ldc + n],            v0);
                atomicAdd(&C[(size_t)m * ldc + n + 1],        v1);
                atomicAdd(&C[(size_t)(m + 8) * ldc + n],      v2);
                atomicAdd(&C[(size_t)(m + 8) * ldc + n + 1],  v3);
            } else {
                *(float2*)&C[(size_t)m * ldc + n]       = make_float2(v0, v1);
                *(float2*)&C[(size_t)(m + 8) * ldc + n] = make_float2(v2, v3);
            }
        }
    }
}

// ---------------- depthwise causal conv1d + silu ----------------
__global__ void conv_silu_kernel(const float* __restrict__ conv_w,
                                 const float* __restrict__ conv_b)
{
    int idx = blockIdx.x * blockDim.x + threadIdx.x;
    int ed = idx & (ED - 1);
    int r  = idx >> 11;
    int b  = r >> 11;
    int l  = r & (SEQLEN - 1);
    float acc = conv_b[ed];
#pragma unroll
    for (int k = 0; k < DCONV; k++) {
        int ls = l - (DCONV - 1) + k;
        if (ls >= 0)
            acc = fmaf(conv_w[ed * DCONV + k],
                       g_xz[(size_t)(b * SEQLEN + ls) * (2 * ED) + ed], acc);
    }
    g_xc[(size_t)idx] = siluf(acc);
}

__global__ void zero_kernel(float* __restrict__ p, int n)
{
    int i = blockIdx.x * blockDim.x + threadIdx.x;
    if (i < n) p[i] = 0.f;
}

// ---------------- chunked selective scan ----------------
__global__ void scan_phase1(const float* __restrict__ A_log)
{
    int idx = blockIdx.x * blockDim.x + threadIdx.x;
    int ed = idx & (ED - 1);
    int c  = (idx >> 11) & (NCH - 1);
    int b  = idx >> 15;

    float A2[NST];
#pragma unroll
    for (int n = 0; n < NST; n++)
        A2[n] = -__expf(A_log[ed * NST + n]) * 1.4426950408889634f;

    float h[NST];
#pragma unroll
    for (int n = 0; n < NST; n++) h[n] = 0.f;
    float sd = 0.f;

    int row0 = b * SEQLEN + c * CH;
    const float* dl = g_delta + (size_t)row0 * ED + ed;
    const float* xv = g_xc    + (size_t)row0 * ED + ed;

    for (int l = 0; l < CH; l++) {
        float d = dl[(size_t)l * ED];
        float x = xv[(size_t)l * ED];
        sd += d;
        float dx = d * x;
        const float4* bb = (const float4*)(g_dbc + (size_t)(row0 + l) * DBCW + DTR);
#pragma unroll
        for (int q = 0; q < 4; q++) {
            float4 bv = bb[q];
            float bw[4] = { bv.x, bv.y, bv.z, bv.w };
#pragma unroll
            for (int jj = 0; jj < 4; jj++) {
                int n = q * 4 + jj;
                float dA = ex2f(A2[n] * d);
                h[n] = fmaf(dA, h[n], bw[jj] * dx);
            }
        }
    }

    size_t ob = ((size_t)(b * ED + ed) * NCH + c) * NST;
#pragma unroll
    for (int n = 0; n < NST; n++) {
        g_hend [ob + n] = h[n];
        g_aprod[ob + n] = ex2f(A2[n] * sd);
    }
}

__global__ void scan_phase2()
{
    int tid = blockIdx.x * blockDim.x + threadIdx.x;
    int n = tid & (NST - 1);
    int e = tid >> 4;
    float h = 0.f;
#pragma unroll
    for (int c = 0; c < NCH; c++) {
        size_t idx = ((size_t)e * NCH + c) * NST + n;
        g_h0[idx] = h;
        h = fmaf(g_aprod[idx], h, g_hend[idx]);
    }
}

__global__ void scan_phase3(const float* __restrict__ A_log,
                            const float* __restrict__ D_param)
{
    int idx = blockIdx.x * blockDim.x + threadIdx.x;
    int ed = idx & (ED - 1);
    int c  = (idx >> 11) & (NCH - 1);
    int b  = idx >> 15;

    float A2[NST];
#pragma unroll
    for (int n = 0; n < NST; n++)
        A2[n] = -__expf(A_log[ed * NST + n]) * 1.4426950408889634f;

    size_t hb = ((size_t)(b * ED + ed) * NCH + c) * NST;
    float h[NST];
#pragma unroll
    for (int n = 0; n < NST; n++) h[n] = g_h0[hb + n];
    float Dv = D_param[ed];

    int row0 = b * SEQLEN + c * CH;
    const float* dl = g_delta + (size_t)row0 * ED + ed;
    const float* xv = g_xc    + (size_t)row0 * ED + ed;

    for (int l = 0; l < CH; l++) {
        float d = dl[(size_t)l * ED];
        float x = xv[(size_t)l * ED];
        float dx = d * x;
        float y = Dv * x;
        const float4* bb = (const float4*)(g_dbc + (size_t)(row0 + l) * DBCW + DTR);
        const float4* cc = (const float4*)(g_dbc + (size_t)(row0 + l) * DBCW + DTR + NST);
#pragma unroll
        for (int q = 0; q < 4; q++) {
            float4 bv = bb[q];
            float4 cv = cc[q];
            float bw[4] = { bv.x, bv.y, bv.z, bv.w };
            float cw[4] = { cv.x, cv.y, cv.z, cv.w };
#pragma unroll
            for (int jj = 0; jj < 4; jj++) {
                int n = q * 4 + jj;
                float dA = ex2f(A2[n] * d);
                h[n] = fmaf(dA, h[n], bw[jj] * dx);
                y = fmaf(h[n], cw[jj], y);
            }
        }
        float z = g_xz[(size_t)(row0 + l) * (2 * ED) + ED + ed];
        g_yz[(size_t)(row0 + l) * ED + ed] = y * siluf(z);
    }
}

// ---------------- launch ----------------
extern "C" void kernel_launch(void* const* d_in, const int* in_sizes, int n_in,
                              void* d_out, int out_size)
{
    const float* x          = (const float*)d_in[0];
    const float* in_proj_w  = (const float*)d_in[1];
    const float* conv_w     = (const float*)d_in[2];
    const float* conv_b     = (const float*)d_in[3];
    const float* x_proj_w   = (const float*)d_in[4];
    const float* dt_w       = (const float*)d_in[5];
    const float* dt_b       = (const float*)d_in[6];
    const float* A_log      = (const float*)d_in[7];
    const float* D_param    = (const float*)d_in[8];
    const float* out_proj_w = (const float*)d_in[9];
    float* out = (float*)d_out;

    float *p_xz, *p_xc, *p_dbc, *p_delta, *p_yz;
    cudaGetSymbolAddress((void**)&p_xz,    g_xz);
    cudaGetSymbolAddress((void**)&p_xc,    g_xc);
    cudaGetSymbolAddress((void**)&p_dbc,   g_dbc);
    cudaGetSymbolAddress((void**)&p_delta, g_delta);
    cudaGetSymbolAddress((void**)&p_yz,    g_yz);

    static int attr_set = 0;
    if (!attr_set) {
        cudaFuncSetAttribute(gemm_mma<0,0,0>, cudaFuncAttributeMaxDynamicSharedMemorySize, MM_SMEM);
        cudaFuncSetAttribute(gemm_mma<0,1,1>, cudaFuncAttributeMaxDynamicSharedMemorySize, MM_SMEM);
        cudaFuncSetAttribute(gemm_mma<1,0,0>, cudaFuncAttributeMaxDynamicSharedMemorySize, MM_SMEM);
        attr_set = 1;
    }

    // G1: xz = x @ in_proj_w^T   (4096 x 4096 x 1024)  [tf32 mma]
    gemm_mma<0,0,0><<<dim3(32, 32, 1), 128, MM_SMEM>>>(
        x, in_proj_w, p_xz, nullptr, ROWS, 2 * ED, DMODEL,
        DMODEL, DMODEL, 2 * ED, DMODEL);

    // depthwise causal conv + silu
    conv_silu_kernel<<<(ROWS * ED) / 256, 256>>>(conv_w, conv_b);

    // G2: dbc = xc @ x_proj_w^T  (4096 x 96 x 2048), split-K=8 atomics [tf32 mma]
    zero_kernel<<<(ROWS * DBCW + 255) / 256, 256>>>(p_dbc, ROWS * DBCW);
    gemm_mma<0,1,1><<<dim3(1, 32, 8), 128, MM_SMEM>>>(
        p_xc, x_proj_w, p_dbc, nullptr, ROWS, DBCW, ED,
        ED, ED, DBCW, ED / 8);

    // G3: delta = softplus(dbc[:, :64] @ dt_w^T + dt_b)  (4096 x 2048 x 64) [tf32 mma]
    gemm_mma<1,0,0><<<dim3(16, 32, 1), 128, MM_SMEM>>>(
        p_dbc, dt_w, p_delta, dt_b, ROWS, ED, DTR,
        DBCW, DTR, ED, DTR);

    // chunked selective scan
    scan_phase1<<<(BATCH * NCH * ED) / 128, 128>>>(A_log);
    scan_phase2<<<(BATCH * ED * NST) / 256, 256>>>();
    scan_phase3<<<(BATCH * NCH * ED) / 128, 128>>>(A_log, D_param);

    // G4: out = yz @ out_proj_w^T  (4096 x 1024 x 2048) [tf32 mma]
    gemm_mma<0,0,0><<<dim3(8, 32, 1), 128, MM_SMEM>>>(
        p_yz, out_proj_w, out, nullptr, ROWS, DMODEL, ED,
        ED, ED, DMODEL, ED);
}

// round 8
// speedup vs baseline: 1.0018x; 1.0018x over previous
#include <cuda_runtime.h>
#include <math.h>
#include <stdint.h>

// ---------------- problem constants ----------------
#define BATCH   2
#define SEQLEN  2048
#define DMODEL  1024
#define ED      2048
#define NST     16
#define DTR     64
#define DCONV   4
#define ROWS    (BATCH*SEQLEN)      // 4096
#define DBCW    (DTR + 2*NST)       // 96
#define NCH     16
#define CH      (SEQLEN/NCH)        // 128

// ---------------- scratch ----------------
__device__ float g_xz   [(size_t)ROWS * 2 * ED];
__device__ float g_xc   [(size_t)ROWS * ED];
__device__ float g_xcr  [(size_t)ROWS * ED];          // tf32-rounded xc for G2
__device__ float g_dbc  [(size_t)ROWS * DBCW];
__device__ float g_dtr  [(size_t)ROWS * DTR];         // rounded dbc[:, :64] for G3
__device__ float g_delta[(size_t)ROWS * ED];
__device__ float g_yz   [(size_t)ROWS * ED];          // rounded by scan_phase3
__device__ float g_aprod[(size_t)BATCH * ED * NCH * NST];
__device__ float g_hend [(size_t)BATCH * ED * NCH * NST];
__device__ float g_h0   [(size_t)BATCH * ED * NCH * NST];
// rounded operand copies
__device__ float g_xr  [(size_t)ROWS * DMODEL];       // x rounded
__device__ float g_w1r [(size_t)2 * ED * DMODEL];     // in_proj_w rounded
__device__ float g_w2r [(size_t)DBCW * ED];           // x_proj_w rounded
__device__ float g_w3r [(size_t)ED * DTR];            // dt_w rounded
__device__ float g_w4r [(size_t)DMODEL * ED];         // out_proj_w rounded

// ---------------- math helpers ----------------
__device__ __forceinline__ float ex2f(float x) {
    float y; asm("ex2.approx.f32 %0, %1;" : "=f"(y) : "f"(x)); return y;
}
__device__ __forceinline__ float siluf(float x) {
    return x / (1.f + ex2f(-1.4426950408889634f * x));
}
__device__ __forceinline__ float softplusf(float x) {
    return (x > 20.f) ? x : log1pf(__expf(x));
}
__device__ __forceinline__ float rndtf(float x) {
    uint32_t u; asm("cvt.rna.tf32.f32 %0, %1;" : "=r"(u) : "f"(x));
    return __uint_as_float(u);
}

// ---------------- PTX helpers (plain sm_80+ features only) ----------------
__device__ __forceinline__ uint32_t smem_u32(const void* p) {
    uint32_t a;
    asm("{ .reg .u64 t; cvta.to.shared.u64 t, %1; cvt.u32.u64 %0, t; }" : "=r"(a) : "l"(p));
    return a;
}
__device__ __forceinline__ void cp16(uint32_t dst, const void* src) {
    asm volatile("cp.async.cg.shared.global [%0], [%1], 16;" :: "r"(dst), "l"(src));
}
__device__ __forceinline__ void cp16z(uint32_t dst, const void* src, uint32_t sz) {
    asm volatile("cp.async.cg.shared.global [%0], [%1], 16, %2;" :: "r"(dst), "l"(src), "r"(sz));
}
__device__ __forceinline__ void cp_commit() {
    asm volatile("cp.async.commit_group;" ::: "memory");
}
template<int N> __device__ __forceinline__ void cp_wait() {
    asm volatile("cp.async.wait_group %0;" :: "n"(N) : "memory");
}
__device__ __forceinline__ void mma8(float* c, const uint32_t* a, const uint32_t* b) {
    asm volatile(
        "mma.sync.aligned.m16n8k8.row.col.f32.tf32.tf32.f32 "
        "{%0,%1,%2,%3}, {%4,%5,%6,%7}, {%8,%9}, {%0,%1,%2,%3};"
        : "+f"(c[0]), "+f"(c[1]), "+f"(c[2]), "+f"(c[3])
        : "r"(a[0]), "r"(a[1]), "r"(a[2]), "r"(a[3]), "r"(b[0]), "r"(b[1]));
}

// ---------------- tf32 mma.sync GEMM (pre-rounded operands, no CVT in loop) ----
// C[M,N] = A[M,K] @ B[N,K]^T.  128x128 CTA tile, 8 warps (2m x 4n), 64x32 warp
// tile, BK=16, 4-stage cp.async ring, smem stride 20 (conflict-free frags).
// EPI=1: softplus(acc + bias[n]).  ATOMIC=1: atomicAdd (split-K).  GUARDN=1: N tile guard.
#define MM_STG_F   (128 * 20)              // floats per matrix per stage
#define MM_SMEM    (4 * 2 * MM_STG_F * 4)  // 81920 bytes

template<int EPI, int ATOMIC, int GUARDN>
__global__ void __launch_bounds__(256, 2)
gemm_mma(const float* __restrict__ A, const float* __restrict__ B,
         float* __restrict__ C, const float* __restrict__ bias,
         int M, int N, int K, int lda, int ldb, int ldc, int kSlice)
{
    extern __shared__ __align__(128) float sm[];
    const uint32_t sb = smem_u32(sm);
    const int tid  = threadIdx.x;
    const int lane = tid & 31;
    const int wid  = tid >> 5;           // 0..7
    const int wm   = wid >> 2;           // 0..1
    const int wn   = wid & 3;            // 0..3
    const int g    = lane >> 2;          // 0..7
    const int j    = lane & 3;           // 0..3
    const int mBlk = blockIdx.y * 128;
    const int nBlk = blockIdx.x * 128;
    const int kBeg = blockIdx.z * kSlice;
    const int T    = kSlice >> 4;

    float acc[4][4][4];
#pragma unroll
    for (int a = 0; a < 4; a++)
#pragma unroll
        for (int b = 0; b < 4; b++)
#pragma unroll
            for (int c = 0; c < 4; c++) acc[a][b][c] = 0.f;

    auto load_tile = [&](int kt, int s) {
        const int k0 = kBeg + kt * 16;
        const uint32_t aB = sb + (uint32_t)s * (2 * MM_STG_F * 4);
        const uint32_t bB = aB + MM_STG_F * 4;
#pragma unroll
        for (int i = 0; i < 2; i++) {
            int ch  = tid + i * 256;     // 0..511
            int row = ch >> 2;           // 0..127
            int c4  = ch & 3;            // 16B chunk
            cp16(aB + row * 80 + c4 * 16,
                 A + (size_t)(mBlk + row) * lda + k0 + c4 * 4);
            if (GUARDN) {
                int brow = nBlk + row;
                int bcl  = min(brow, N - 1);
                uint32_t sz = (brow < N) ? 16u : 0u;
                cp16z(bB + row * 80 + c4 * 16,
                      B + (size_t)bcl * ldb + k0 + c4 * 4, sz);
            } else {
                cp16(bB + row * 80 + c4 * 16,
                     B + (size_t)(nBlk + row) * ldb + k0 + c4 * 4);
            }
        }
        cp_commit();
    };

    load_tile(0, 0);
    load_tile(1, 1);
    load_tile(2, 2);

    for (int kt = 0; kt < T; kt++) {
        cp_wait<2>();
        __syncthreads();

        if (kt + 3 < T) load_tile(kt + 3, (kt + 3) & 3);
        cp_commit();     // always-commit -> loop-invariant wait count

        const int buf = kt & 3;
        const uint32_t* As = (const uint32_t*)(sm + (size_t)buf * (2 * MM_STG_F));
        const uint32_t* Bs = As + MM_STG_F;

#pragma unroll
        for (int ks = 0; ks < 2; ks++) {
            const int k0 = ks * 8;
            uint32_t af[4][4], bf[4][2];
#pragma unroll
            for (int mt = 0; mt < 4; mt++) {
                int r = wm * 64 + mt * 16 + g;
                af[mt][0] = As[r * 20 + k0 + j];
                af[mt][1] = As[(r + 8) * 20 + k0 + j];
                af[mt][2] = As[r * 20 + k0 + j + 4];
                af[mt][3] = As[(r + 8) * 20 + k0 + j + 4];
            }
#pragma unroll
            for (int nt = 0; nt < 4; nt++) {
                int r = wn * 32 + nt * 8 + g;
                bf[nt][0] = Bs[r * 20 + k0 + j];
                bf[nt][1] = Bs[r * 20 + k0 + j + 4];
            }
#pragma unroll
            for (int mt = 0; mt < 4; mt++)
#pragma unroll
                for (int nt = 0; nt < 4; nt++)
                    mma8(acc[mt][nt], af[mt], bf[nt]);
        }
    }

    // epilogue
#pragma unroll
    for (int mt = 0; mt < 4; mt++) {
#pragma unroll
        for (int nt = 0; nt < 4; nt++) {
            int m = mBlk + wm * 64 + mt * 16 + g;
            int n = nBlk + wn * 32 + nt * 8 + 2 * j;
            float* cv = acc[mt][nt];
            if (GUARDN && n >= N) continue;
            float v0 = cv[0], v1 = cv[1], v2 = cv[2], v3 = cv[3];
            if (EPI == 1) {
                float b0 = bias[n], b1 = bias[n + 1];
                v0 = softplusf(v0 + b0); v1 = softplusf(v1 + b1);
                v2 = softplusf(v2 + b0); v3 = softplusf(v3 + b1);
            }
            if (ATOMIC) {
                atomicAdd(&C[(size_t)m * ldc + n],            v0);
                atomicAdd(&C[(size_t)m * ldc + n + 1],        v1);
                atomicAdd(&C[(size_t)(m + 8) * ldc + n],      v2);
                atomicAdd(&C[(size_t)(m + 8) * ldc + n + 1],  v3);
            } else {
                *(float2*)&C[(size_t)m * ldc + n]       = make_float2(v0, v1);
                *(float2*)&C[(size_t)(m + 8) * ldc + n] = make_float2(v2, v3);
            }
        }
    }
}

// ---------------- tf32 rounding pass (vectorized) ----------------
__global__ void round_tf32_kernel(const float4* __restrict__ in,
                                  float4* __restrict__ out, int n4)
{
    int i = blockIdx.x * blockDim.x + threadIdx.x;
    if (i < n4) {
        float4 v = in[i];
        v.x = rndtf(v.x); v.y = rndtf(v.y); v.z = rndtf(v.z); v.w = rndtf(v.w);
        out[i] = v;
    }
}

// extract + round dbc[:, 0:64] -> dense [ROWS, 64]
__global__ void dtr_round_kernel()
{
    int idx = blockIdx.x * blockDim.x + threadIdx.x;  // ROWS*DTR
    int row = idx >> 6;
    int col = idx & 63;
    g_dtr[idx] = rndtf(g_dbc[(size_t)row * DBCW + col]);
}

// ---------------- depthwise causal conv1d + silu (writes full + rounded) -----
__global__ void conv_silu_kernel(const float* __restrict__ conv_w,
                                 const float* __restrict__ conv_b)
{
    int idx = blockIdx.x * blockDim.x + threadIdx.x;
    int ed = idx & (ED - 1);
    int r  = idx >> 11;
    int b  = r >> 11;
    int l  = r & (SEQLEN - 1);
    float acc = conv_b[ed];
#pragma unroll
    for (int k = 0; k < DCONV; k++) {
        int ls = l - (DCONV - 1) + k;
        if (ls >= 0)
            acc = fmaf(conv_w[ed * DCONV + k],
                       g_xz[(size_t)(b * SEQLEN + ls) * (2 * ED) + ed], acc);
    }
    float v = siluf(acc);
    g_xc [(size_t)idx] = v;
    g_xcr[(size_t)idx] = rndtf(v);
}

__global__ void zero_kernel(float* __restrict__ p, int n)
{
    int i = blockIdx.x * blockDim.x + threadIdx.x;
    if (i < n) p[i] = 0.f;
}

// ---------------- chunked selective scan ----------------
__global__ void scan_phase1(const float* __restrict__ A_log)
{
    int idx = blockIdx.x * blockDim.x + threadIdx.x;
    int ed = idx & (ED - 1);
    int c  = (idx >> 11) & (NCH - 1);
    int b  = idx >> 15;

    float A2[NST];
#pragma unroll
    for (int n = 0; n < NST; n++)
        A2[n] = -__expf(A_log[ed * NST + n]) * 1.4426950408889634f;

    float h[NST];
#pragma unroll
    for (int n = 0; n < NST; n++) h[n] = 0.f;
    float sd = 0.f;

    int row0 = b * SEQLEN + c * CH;
    const float* dl = g_delta + (size_t)row0 * ED + ed;
    const float* xv = g_xc    + (size_t)row0 * ED + ed;

    for (int l = 0; l < CH; l++) {
        float d = dl[(size_t)l * ED];
        float x = xv[(size_t)l * ED];
        sd += d;
        float dx = d * x;
        const float4* bb = (const float4*)(g_dbc + (size_t)(row0 + l) * DBCW + DTR);
#pragma unroll
        for (int q = 0; q < 4; q++) {
            float4 bv = bb[q];
            float bw[4] = { bv.x, bv.y, bv.z, bv.w };
#pragma unroll
            for (int jj = 0; jj < 4; jj++) {
                int n = q * 4 + jj;
                float dA = ex2f(A2[n] * d);
                h[n] = fmaf(dA, h[n], bw[jj] * dx);
            }
        }
    }

    size_t ob = ((size_t)(b * ED + ed) * NCH + c) * NST;
#pragma unroll
    for (int n = 0; n < NST; n++) {
        g_hend [ob + n] = h[n];
        g_aprod[ob + n] = ex2f(A2[n] * sd);
    }
}

__global__ void scan_phase2()
{
    int tid = blockIdx.x * blockDim.x + threadIdx.x;
    int n = tid & (NST - 1);
    int e = tid >> 4;
    float h = 0.f;
#pragma unroll
    for (int c = 0; c < NCH; c++) {
        size_t idx = ((size_t)e * NCH + c) * NST + n;
        g_h0[idx] = h;
        h = fmaf(g_aprod[idx], h, g_hend[idx]);
    }
}

__global__ void scan_phase3(const float* __restrict__ A_log,
                            const float* __restrict__ D_param)
{
    int idx = blockIdx.x * blockDim.x + threadIdx.x;
    int ed = idx & (ED - 1);
    int c  = (idx >> 11) & (NCH - 1);
    int b  = idx >> 15;

    float A2[NST];
#pragma unroll
    for (int n = 0; n < NST; n++)
        A2[n] = -__expf(A_log[ed * NST + n]) * 1.4426950408889634f;

    size_t hb = ((size_t)(b * ED + ed) * NCH + c) * NST;
    float h[NST];
#pragma unroll
    for (int n = 0; n < NST; n++) h[n] = g_h0[hb + n];
    float Dv = D_param[ed];

    int row0 = b * SEQLEN + c * CH;
    const float* dl = g_delta + (size_t)row0 * ED + ed;
    const float* xv = g_xc    + (size_t)row0 * ED + ed;

    for (int l = 0; l < CH; l++) {
        float d = dl[(size_t)l * ED];
        float x = xv[(size_t)l * ED];
        float dx = d * x;
        float y = Dv * x;
        const float4* bb = (const float4*)(g_dbc + (size_t)(row0 + l) * DBCW + DTR);
        const float4* cc = (const float4*)(g_dbc + (size_t)(row0 + l) * DBCW + DTR + NST);
#pragma unroll
        for (int q = 0; q < 4; q++) {
            float4 bv = bb[q];
            float4 cv = cc[q];
            float bw[4] = { bv.x, bv.y, bv.z, bv.w };
            float cw[4] = { cv.x, cv.y, cv.z, cv.w };
#pragma unroll
            for (int jj = 0; jj < 4; jj++) {
                int n = q * 4 + jj;
                float dA = ex2f(A2[n] * d);
                h[n] = fmaf(dA, h[n], bw[jj] * dx);
                y = fmaf(h[n], cw[jj], y);
            }
        }
        float z = g_xz[(size_t)(row0 + l) * (2 * ED) + ED + ed];
        // store tf32-rounded: G4 is the only consumer (bit-identical to in-loop cvt)
        g_yz[(size_t)(row0 + l) * ED + ed] = rndtf(y * siluf(z));
    }
}

// ---------------- launch ----------------
extern "C" void kernel_launch(void* const* d_in, const int* in_sizes, int n_in,
                              void* d_out, int out_size)
{
    const float* x          = (const float*)d_in[0];
    const float* in_proj_w  = (const float*)d_in[1];
    const float* conv_w     = (const float*)d_in[2];
    const float* conv_b     = (const float*)d_in[3];
    const float* x_proj_w   = (const float*)d_in[4];
    const float* dt_w       = (const float*)d_in[5];
    const float* dt_b       = (const float*)d_in[6];
    const float* A_log      = (const float*)d_in[7];
    const float* D_param    = (const float*)d_in[8];
    const float* out_proj_w = (const float*)d_in[9];
    float* out = (float*)d_out;

    float *p_xz, *p_dbc, *p_delta, *p_yz;
    float *p_xr, *p_w1r, *p_w2r, *p_w3r, *p_w4r, *p_xcr, *p_dtr;
    cudaGetSymbolAddress((void**)&p_xz,    g_xz);
    cudaGetSymbolAddress((void**)&p_dbc,   g_dbc);
    cudaGetSymbolAddress((void**)&p_delta, g_delta);
    cudaGetSymbolAddress((void**)&p_yz,    g_yz);
    cudaGetSymbolAddress((void**)&p_xr,    g_xr);
    cudaGetSymbolAddress((void**)&p_w1r,   g_w1r);
    cudaGetSymbolAddress((void**)&p_w2r,   g_w2r);
    cudaGetSymbolAddress((void**)&p_w3r,   g_w3r);
    cudaGetSymbolAddress((void**)&p_w4r,   g_w4r);
    cudaGetSymbolAddress((void**)&p_xcr,   g_xcr);
    cudaGetSymbolAddress((void**)&p_dtr,   g_dtr);

    static int attr_set = 0;
    if (!attr_set) {
        cudaFuncSetAttribute(gemm_mma<0,0,0>, cudaFuncAttributeMaxDynamicSharedMemorySize, MM_SMEM);
        cudaFuncSetAttribute(gemm_mma<0,1,1>, cudaFuncAttributeMaxDynamicSharedMemorySize, MM_SMEM);
        cudaFuncSetAttribute(gemm_mma<1,0,0>, cudaFuncAttributeMaxDynamicSharedMemorySize, MM_SMEM);
        attr_set = 1;
    }

    // pre-round GEMM operands to tf32 (bit-identical to in-loop cvt)
    {
        int n4;
        n4 = (ROWS * DMODEL) / 4;
        round_tf32_kernel<<<(n4 + 255) / 256, 256>>>((const float4*)x, (float4*)p_xr, n4);
        n4 = (2 * ED * DMODEL) / 4;
        round_tf32_kernel<<<(n4 + 255) / 256, 256>>>((const float4*)in_proj_w, (float4*)p_w1r, n4);
        n4 = (DBCW * ED) / 4;
        round_tf32_kernel<<<(n4 + 255) / 256, 256>>>((const float4*)x_proj_w, (float4*)p_w2r, n4);
        n4 = (ED * DTR) / 4;
        round_tf32_kernel<<<(n4 + 255) / 256, 256>>>((const float4*)dt_w, (float4*)p_w3r, n4);
        n4 = (DMODEL * ED) / 4;
        round_tf32_kernel<<<(n4 + 255) / 256, 256>>>((const float4*)out_proj_w, (float4*)p_w4r, n4);
    }

    // G1: xz = x @ in_proj_w^T   (4096 x 4096 x 1024)
    gemm_mma<0,0,0><<<dim3(32, 32, 1), 256, MM_SMEM>>>(
        p_xr, p_w1r, p_xz, nullptr, ROWS, 2 * ED, DMODEL,
        DMODEL, DMODEL, 2 * ED, DMODEL);

    // depthwise causal conv + silu (full + rounded outputs)
    conv_silu_kernel<<<(ROWS * ED) / 256, 256>>>(conv_w, conv_b);

    // G2: dbc = xc @ x_proj_w^T  (4096 x 96 x 2048), split-K=8 atomics
    zero_kernel<<<(ROWS * DBCW + 255) / 256, 256>>>(p_dbc, ROWS * DBCW);
    gemm_mma<0,1,1><<<dim3(1, 32, 8), 256, MM_SMEM>>>(
        p_xcr, p_w2r, p_dbc, nullptr, ROWS, DBCW, ED,
        ED, ED, DBCW, ED / 8);

    // round + densify dbc[:, :64] for G3
    dtr_round_kernel<<<(ROWS * DTR) / 256, 256>>>();

    // G3: delta = softplus(dtr @ dt_w^T + dt_b)  (4096 x 2048 x 64)
    gemm_mma<1,0,0><<<dim3(16, 32, 1), 256, MM_SMEM>>>(
        p_dtr, p_w3r, p_delta, dt_b, ROWS, ED, DTR,
        DTR, DTR, ED, DTR);

    // chunked selective scan
    scan_phase1<<<(BATCH * NCH * ED) / 128, 128>>>(A_log);
    scan_phase2<<<(BATCH * ED * NST) / 256, 256>>>();
    scan_phase3<<<(BATCH * NCH * ED) / 128, 128>>>(A_log, D_param);

    // G4: out = yz @ out_proj_w^T  (4096 x 1024 x 2048)
    gemm_mma<0,0,0><<<dim3(8, 32, 1), 256, MM_SMEM>>>(
        p_yz, p_w4r, out, nullptr, ROWS, DMODEL, ED,
        ED, ED, DMODEL, ED);
}